// round 14
// baseline (speedup 1.0000x reference)
#include <cuda_runtime.h>
#include <cuda_bf16.h>
#include <math.h>

// Problem constants
#define BB 32
#define SS 512
#define II 512
#define HH 1024
#define OO 512
#define G4 4096          // 4*H
#define LDW 1536         // I+H, row stride of the gate weight matrices
#define NB 128           // persistent scan blocks (1 per SM, <= 148)

// packed fp32x2 FMA
#define FMA2(acc, a, b) \
    asm("fma.rn.f32x2 %0, %1, %2, %0;" : "+l"(acc) : "l"(a), "l"(b))

__device__ __forceinline__ float2 unpack2(unsigned long long v) {
    float2 r;
    asm("mov.b64 {%0, %1}, %2;" : "=f"(r.x), "=f"(r.y) : "l"(v));
    return r;
}
__device__ __forceinline__ unsigned long long dup2(float x) {
    unsigned long long r;
    asm("mov.b64 %0, {%1, %1};" : "=l"(r) : "f"(x));
    return r;
}

// -------------------- scratch (device globals; no allocations) --------------------
__device__ float g_xg[(size_t)SS * BB * G4];   // [b][s][4H] row m = b*S+s   (256 MB)
__device__ float g_hs[(size_t)BB * SS * HH];   // [b][s][H]  row m = b*S+s   (64 MB)
// h double buffers, duplicated-pair layout:
//   hd[k2][b] = float4(h[b][2k2], h[b][2k2], h[b][2k2+1], h[b][2k2+1])
__device__ float g_hdA[(HH / 2) * BB * 4];     // 256 KB
__device__ float g_hdB[(HH / 2) * BB * 4];
__device__ float g_c [BB * HH];                // c transposed: [u][b]
__device__ unsigned g_bar;                     // CG-style barrier counter

// -------------------- utility kernels --------------------
__global__ void scan_init(float* __restrict__ hA, unsigned* __restrict__ bar) {
    int i = blockIdx.x * blockDim.x + threadIdx.x;
    for (int j = i; j < (HH / 2) * BB * 4; j += NB * 256) hA[j] = 0.0f;
    if (i == 0) *bar = 0u;
}

// final h in dup layout, c in [u][b]; emit [b][H] for both
__global__ void copy_finals(const float* __restrict__ ht, const float* __restrict__ c,
                            float* __restrict__ out) {
    int i = blockIdx.x * blockDim.x + threadIdx.x;   // i = b*HH + u
    if (i < BB * HH) {
        int b = i >> 10, u = i & (HH - 1);
        out[i]           = ht[(u >> 1) * 128 + b * 4 + (u & 1) * 2];
        out[BB * HH + i] = c[u * BB + b];
    }
}

// -------------------- SGEMM: C[M,N] = A[M,K] @ Bw[N,K]^T + bias[N] --------------------
// BM=BN=128, BK=16, 256 threads, 8x8 per thread. (At fp32 SIMT peak.)
__global__ __launch_bounds__(256, 2)
void sgemm_tn(int M, int N, int K,
              const float* __restrict__ A, int lda,
              const float* __restrict__ Bw, int ldb,
              const float* __restrict__ bias,
              float* __restrict__ C, int ldc) {
    __shared__ float As[16][128];
    __shared__ float Bs[16][128];

    const int tid = threadIdx.x;
    const int rowBase = blockIdx.y * 128;
    const int colBase = blockIdx.x * 128;

    const int ldRow = tid >> 2;
    const int ldK   = (tid & 3) << 2;

    const int tx = tid & 15;
    const int ty = tid >> 4;

    unsigned long long acc[8][4];
#pragma unroll
    for (int i = 0; i < 8; i++)
#pragma unroll
        for (int j = 0; j < 4; j++) acc[i][j] = 0ull;

    for (int k0 = 0; k0 < K; k0 += 16) {
#pragma unroll
        for (int r = 0; r < 128; r += 64) {
            float4 va = *reinterpret_cast<const float4*>(
                A + (size_t)(rowBase + ldRow + r) * lda + k0 + ldK);
            As[ldK + 0][ldRow + r] = va.x;
            As[ldK + 1][ldRow + r] = va.y;
            As[ldK + 2][ldRow + r] = va.z;
            As[ldK + 3][ldRow + r] = va.w;
        }
#pragma unroll
        for (int r = 0; r < 128; r += 64) {
            float4 vb = *reinterpret_cast<const float4*>(
                Bw + (size_t)(colBase + ldRow + r) * ldb + k0 + ldK);
            Bs[ldK + 0][ldRow + r] = vb.x;
            Bs[ldK + 1][ldRow + r] = vb.y;
            Bs[ldK + 2][ldRow + r] = vb.z;
            Bs[ldK + 3][ldRow + r] = vb.w;
        }
        __syncthreads();

#pragma unroll
        for (int kk = 0; kk < 16; kk++) {
            float ar[8];
#pragma unroll
            for (int i = 0; i < 8; i++) ar[i] = As[kk][ty * 8 + i];
            const ulonglong2* bp =
                reinterpret_cast<const ulonglong2*>(&Bs[kk][tx * 8]);
            ulonglong2 b01 = bp[0];
            ulonglong2 b23 = bp[1];
#pragma unroll
            for (int i = 0; i < 8; i++) {
                unsigned long long a2 = dup2(ar[i]);
                FMA2(acc[i][0], a2, b01.x);
                FMA2(acc[i][1], a2, b01.y);
                FMA2(acc[i][2], a2, b23.x);
                FMA2(acc[i][3], a2, b23.y);
            }
        }
        __syncthreads();
    }

#pragma unroll
    for (int i = 0; i < 8; i++) {
        float* crow = C + (size_t)(rowBase + ty * 8 + i) * ldc + colBase + tx * 8;
#pragma unroll
        for (int j = 0; j < 2; j++) {
            float2 p0 = unpack2(acc[i][2 * j + 0]);
            float2 p1 = unpack2(acc[i][2 * j + 1]);
            float4 v;
            v.x = p0.x + bias[colBase + tx * 8 + 4 * j + 0];
            v.y = p0.y + bias[colBase + tx * 8 + 4 * j + 1];
            v.z = p1.x + bias[colBase + tx * 8 + 4 * j + 2];
            v.w = p1.y + bias[colBase + tx * 8 + 4 * j + 3];
            *reinterpret_cast<float4*>(crow + 4 * j) = v;
        }
    }
}

// -------------------- grid-wide barrier (cooperative-groups sync_grids pattern) ----
__device__ __forceinline__ void grid_sync(unsigned* bar) {
    __syncthreads();
    if (threadIdx.x == 0) {
        __threadfence();
        unsigned add = (blockIdx.x == 0) ? (0x80000000u - (NB - 1)) : 1u;
        unsigned old = atomicAdd(bar, add);
        while (((old ^ *(volatile unsigned*)bar) & 0x80000000u) == 0u) { }
        __threadfence();
    }
    __syncthreads();
}

// -------------------- persistent recurrent scan --------------------
// 128 blocks x 256 threads, one block per SM, all 512 steps in one launch.
// Block bk owns hidden units u in [bk*8, bk*8+8). Lane map: lane = b_loc*8+u_off;
// warp w covers ALL 8 units x 4 batches b in [4w, 4w+4).
// Weights in smem, layout wsm[k][u8][gate4] (float): one LDS.128 per k delivers
// (wf,wi,wo,wc) for lane's u -- lanes 0..7 read a dense 128 B line (zero waste),
// broadcast to the 4 b-groups. Crossbar traffic = weights only (8192 wf/step).
// h in global dup-pair layout hd[k2][b] = (h,h,h',h'): one LDG.128 = two FMA2
// operands, 64 B distinct per warp-iter -> 16 MB/step of L2 (8x less than R12).
// FMA2 pairs gates (f,i) and (o,c). c stays in a register for all 512 steps.
#define SCAN_SMEM 131072   // 128 KB weights

__global__ __launch_bounds__(256, 1)
void lstm_scan(const float* __restrict__ xg,
               float* bufA, float* bufB,
               float* __restrict__ cfin, float* __restrict__ hs,
               unsigned* bar,
               const float* __restrict__ Wf, const float* __restrict__ Wi,
               const float* __restrict__ Wo, const float* __restrict__ Wc) {
    extern __shared__ float wsm[];   // [1024][8][4] floats = 128 KB
    const int tid   = threadIdx.x;
    const int bk    = blockIdx.x;
    const int lane  = tid & 31;
    const int w     = tid >> 5;
    const int u_off = lane & 7;
    const int b_loc = lane >> 3;             // 0..3
    const int u     = bk * 8 + u_off;
    const int b     = w * 4 + b_loc;

    // one-time: weights -> smem, layout [k][u][g] (dense STS; scattered LDG ok once)
    for (int i = tid; i < 32768; i += 256) {
        int k = i >> 5;
        int uu = (i >> 2) & 7;
        int g = i & 3;
        const float* Wsrc = (g == 0) ? Wf : (g == 1) ? Wi : (g == 2) ? Wo : Wc;
        wsm[i] = Wsrc[(size_t)(bk * 8 + uu) * LDW + II + k];
    }
    __syncthreads();

    // per-lane weight stream: wsm as ulonglong2[k*8 + u_off]
    const ulonglong2* wq = reinterpret_cast<const ulonglong2*>(wsm) + u_off;

    float creg = 0.0f;
    float* cur = bufA;
    float* nxt = bufB;

    for (int s = 0; s < SS; s++) {
        // this step's xg tail values (issued early, consumed at the end)
        const float* xr = xg + ((size_t)b * SS + s) * G4;
        float xf = xr[u];
        float xi = xr[HH + u];
        float xo = xr[2 * HH + u];
        float xc = xr[3 * HH + u];

        // accumulators: (f,i) and (o,c) pairs, even/odd k split for ILP
        unsigned long long aFI0 = 0ull, aOC0 = 0ull, aFI1 = 0ull, aOC1 = 0ull;

        const ulonglong2* hq = reinterpret_cast<const ulonglong2*>(cur) + b;

        // 8-deep h prefetch ring; hq[k2*32] = (h_even,h_even | h_odd,h_odd)
        ulonglong2 ring[8];
#pragma unroll
        for (int j = 0; j < 8; j++) ring[j] = hq[j * 32];

#pragma unroll 8
        for (int k2 = 0; k2 < 504; k2++) {
            ulonglong2 hv = ring[k2 & 7];
            ring[k2 & 7] = hq[(k2 + 8) * 32];
            ulonglong2 w0 = wq[(2 * k2 + 0) * 8];   // (wf,wi | wo,wc) at k even
            ulonglong2 w1 = wq[(2 * k2 + 1) * 8];   // ... at k odd
            FMA2(aFI0, w0.x, hv.x);
            FMA2(aOC0, w0.y, hv.x);
            FMA2(aFI1, w1.x, hv.y);
            FMA2(aOC1, w1.y, hv.y);
        }
#pragma unroll
        for (int k2 = 504; k2 < 512; k2++) {
            ulonglong2 hv = ring[k2 & 7];
            ulonglong2 w0 = wq[(2 * k2 + 0) * 8];
            ulonglong2 w1 = wq[(2 * k2 + 1) * 8];
            FMA2(aFI0, w0.x, hv.x);
            FMA2(aOC0, w0.y, hv.x);
            FMA2(aFI1, w1.x, hv.y);
            FMA2(aOC1, w1.y, hv.y);
        }

        float2 fi0 = unpack2(aFI0), fi1 = unpack2(aFI1);
        float2 oc0 = unpack2(aOC0), oc1 = unpack2(aOC1);
        float gf = fi0.x + fi1.x + xf;
        float gi = fi0.y + fi1.y + xi;
        float go = oc0.x + oc1.x + xo;
        float gc = oc0.y + oc1.y + xc;

        float f  = 1.0f / (1.0f + expf(-gf));
        float ig = 1.0f / (1.0f + expf(-gi));
        float og = 1.0f / (1.0f + expf(-go));

        float cn = f * creg + ig * tanhf(gc);
        creg = cn;
        float hn = og * tanhf(cn);

        // h_next in dup-pair layout: float2 slot (u>>1)*64 + b*2 + (u&1)
        reinterpret_cast<float2*>(nxt)[(u >> 1) * 64 + b * 2 + (u & 1)] =
            make_float2(hn, hn);

        grid_sync(bar);

        // hs store off the critical path (not consumed until phase 3)
        hs[((size_t)b * SS + s) * HH + u] = hn;

        float* tmp = cur; cur = nxt; nxt = tmp;
    }
    // after 512 steps (even count) final h sits in bufA; write final c
    cfin[u * BB + b] = creg;
}

// -------------------- launch --------------------
extern "C" void kernel_launch(void* const* d_in, const int* in_sizes, int n_in,
                              void* d_out, int out_size) {
    (void)in_sizes; (void)n_in;
    const float* x    = (const float*)d_in[0];
    const float* Wf_w = (const float*)d_in[1];
    const float* Wf_b = (const float*)d_in[2];
    const float* Wi_w = (const float*)d_in[3];
    const float* Wi_b = (const float*)d_in[4];
    const float* Wo_w = (const float*)d_in[5];
    const float* Wo_b = (const float*)d_in[6];
    const float* Wc_w = (const float*)d_in[7];
    const float* Wc_b = (const float*)d_in[8];
    const float* out_w = (const float*)d_in[9];
    const float* out_b = (const float*)d_in[10];

    float *xg, *hs, *hA, *hB, *c;
    unsigned* bar;
    cudaGetSymbolAddress((void**)&xg, g_xg);
    cudaGetSymbolAddress((void**)&hs, g_hs);
    cudaGetSymbolAddress((void**)&hA, g_hdA);
    cudaGetSymbolAddress((void**)&hB, g_hdB);
    cudaGetSymbolAddress((void**)&c,  g_c);
    cudaGetSymbolAddress((void**)&bar, g_bar);

    cudaFuncSetAttribute(lstm_scan, cudaFuncAttributeMaxDynamicSharedMemorySize, SCAN_SMEM);

    // reset h0 and barrier counter (deterministic across graph replays)
    scan_init<<<NB, 256>>>(hA, bar);

    const int M = BB * SS;  // 16384, row m = b*S+s

    // phase 1: xg[m][g] = x @ Wx^T + b   (4 gate GEMMs: N=1024, K=512)
    {
        dim3 grid(HH / 128, M / 128);
        sgemm_tn<<<grid, 256>>>(M, HH, II, x, II, Wf_w, LDW, Wf_b, xg + 0 * HH, G4);
        sgemm_tn<<<grid, 256>>>(M, HH, II, x, II, Wi_w, LDW, Wi_b, xg + 1 * HH, G4);
        sgemm_tn<<<grid, 256>>>(M, HH, II, x, II, Wo_w, LDW, Wo_b, xg + 2 * HH, G4);
        sgemm_tn<<<grid, 256>>>(M, HH, II, x, II, Wc_w, LDW, Wc_b, xg + 3 * HH, G4);
    }

    // phase 2: ONE persistent launch for all 512 steps
    lstm_scan<<<NB, 256, SCAN_SMEM>>>(xg, hA, hB, c, hs, bar,
                                      Wf_w, Wi_w, Wo_w, Wc_w);

    // phase 3: final = hs @ out_w^T + out_b  (M=16384, N=512, K=1024)
    {
        dim3 grid(OO / 128, M / 128);
        sgemm_tn<<<grid, 256>>>(M, OO, HH, hs, HH, out_w, HH, out_b, (float*)d_out, OO);
    }

    // tail outputs (h_fin, c_fin) if the flattened output includes them
    long long need = (long long)BB * SS * OO + 2LL * BB * HH;
    if ((long long)out_size >= need) {
        copy_finals<<<NB, 256>>>(hA, c, (float*)d_out + (size_t)BB * SS * OO);
    }
}